// round 1
// baseline (speedup 1.0000x reference)
#include <cuda_runtime.h>
#include <math.h>

// Problem constants
#define BB    2
#define SS    1024
#define DD    1024
#define NH    16
#define HD    64
#define NL    12
#define DFF   4096
#define RH    128
#define VOC   32000
#define MM    (BB*SS)          // 2048 tokens
#define BHT   (BB*NH)          // 32 batch-heads

// ---------------- static device scratch (no allocations allowed) ----------------
__device__ float g_h [MM*DD];
__device__ float g_h1[MM*DD];
__device__ float g_t [MM*DD];
__device__ float g_q [MM*DD];
__device__ float g_k [MM*DD];
__device__ float g_v [MM*DD];
__device__ float g_a [MM*DD];
__device__ float g_ht[MM*DD];
__device__ float g_f1[MM*DFF];
__device__ float g_zr[MM*RH];
__device__ float g_sc[(size_t)BHT*SS*SS];   // 128 MB attention scores
__device__ unsigned char g_skip[MM];
__device__ int g_cnt[3];

// ---------------- init / counters ----------------
__global__ void zero_cnt_kernel() {
    if (threadIdx.x < 3) g_cnt[threadIdx.x] = 0;
}

// ---------------- embedding + positional encoding ----------------
// h[tok][d] = emb[x[tok]][d]*sqrt(D) + pe(s,d)
__global__ __launch_bounds__(256) void embed_kernel(const int* __restrict__ x,
                                                    const float* __restrict__ emb) {
    int tok = blockIdx.x;
    int s = tok % SS;
    int id = x[tok];
    int d0 = threadIdx.x * 4;
    float4 ev = *(const float4*)(emb + (size_t)id * DD + d0);
    float o[4] = {ev.x, ev.y, ev.z, ev.w};
#pragma unroll
    for (int j = 0; j < 4; j++) {
        int d = d0 + j;
        float ang = (float)s * expf((float)(d & ~1) * (-9.210340371976184f / 1024.0f));
        float pe = (d & 1) ? cosf(ang) : sinf(ang);
        o[j] = o[j] * 32.0f + pe;   // sqrt(1024)=32
    }
    *(float4*)(g_h + (size_t)tok * DD + d0) = make_float4(o[0], o[1], o[2], o[3]);
}

// ---------------- generic tiled SGEMM: C = [res +] A(MxK) @ B(KxN) [+bias] [relu] --------
// Requires M%128==0, N%64==0, K%16==0, K%4==0, N%4==0 (all call sites satisfy this).
__global__ __launch_bounds__(256) void sgemm_kernel(const float* __restrict__ A,
                                                    const float* __restrict__ B,
                                                    const float* __restrict__ bias,
                                                    const float* __restrict__ res,
                                                    float* __restrict__ C,
                                                    int M, int N, int K, int relu) {
    __shared__ float Ast[16][128];   // [k][m]
    __shared__ float Bs [16][64];    // [k][n]
    int tid = threadIdx.x;
    int bm = blockIdx.y * 128, bn = blockIdx.x * 64;
    int tx = tid & 15, ty = tid >> 4;
    int m0 = ty * 8, n0 = tx * 4;
    float acc[8][4];
#pragma unroll
    for (int i = 0; i < 8; i++)
#pragma unroll
        for (int j = 0; j < 4; j++) acc[i][j] = 0.f;

    int arow = tid >> 2;       // 0..63
    int ak4  = (tid & 3) * 4;  // 0,4,8,12
    int bk   = tid >> 4;       // 0..15
    int bc4  = (tid & 15) * 4; // 0..60

    for (int kb = 0; kb < K; kb += 16) {
#pragma unroll
        for (int p = 0; p < 2; p++) {
            int r = arow + p * 64;
            float4 av = *(const float4*)(A + (size_t)(bm + r) * K + kb + ak4);
            Ast[ak4 + 0][r] = av.x;
            Ast[ak4 + 1][r] = av.y;
            Ast[ak4 + 2][r] = av.z;
            Ast[ak4 + 3][r] = av.w;
        }
        *(float4*)&Bs[bk][bc4] = *(const float4*)(B + (size_t)(kb + bk) * N + bn + bc4);
        __syncthreads();
#pragma unroll
        for (int k = 0; k < 16; k++) {
            float4 a0 = *(float4*)&Ast[k][m0];
            float4 a1 = *(float4*)&Ast[k][m0 + 4];
            float4 bv = *(float4*)&Bs[k][n0];
            float am[8] = {a0.x, a0.y, a0.z, a0.w, a1.x, a1.y, a1.z, a1.w};
            float bb[4] = {bv.x, bv.y, bv.z, bv.w};
#pragma unroll
            for (int i = 0; i < 8; i++)
#pragma unroll
                for (int j = 0; j < 4; j++) acc[i][j] += am[i] * bb[j];
        }
        __syncthreads();
    }
#pragma unroll
    for (int i = 0; i < 8; i++) {
        int m = bm + m0 + i;
#pragma unroll
        for (int j = 0; j < 4; j++) {
            int n = bn + n0 + j;
            float v = acc[i][j];
            if (bias) v += bias[n];
            if (res)  v += res[(size_t)m * N + n];
            if (relu) v = fmaxf(v, 0.f);
            C[(size_t)m * N + n] = v;
        }
    }
}

// ---------------- attention: scores = Q Kt / 8 with causal mask ----------------
__global__ __launch_bounds__(256) void attn_scores_kernel() {
    int kt = blockIdx.x, qt = blockIdx.y, bh = blockIdx.z;
    int b = bh >> 4, hh = bh & 15;
    int tid = threadIdx.x;
    float* sc = g_sc + ((size_t)bh * SS + qt * 64) * SS + kt * 64;
    if (kt > qt) {  // fully masked tile
        for (int i = tid; i < 64 * 64; i += 256)
            sc[(size_t)(i >> 6) * SS + (i & 63)] = -1e30f;
        return;
    }
    __shared__ float Qs[64][65];
    __shared__ float Ks[64][65];
    const float* qb = g_q + ((size_t)(b * SS + qt * 64)) * DD + hh * HD;
    const float* kb = g_k + ((size_t)(b * SS + kt * 64)) * DD + hh * HD;
    for (int i = tid; i < 64 * 64; i += 256) {
        int r = i >> 6, c = i & 63;
        Qs[r][c] = qb[(size_t)r * DD + c];
        Ks[r][c] = kb[(size_t)r * DD + c];
    }
    __syncthreads();
    int tx = tid & 15, ty = tid >> 4;
    int q0 = ty * 4, k0 = tx * 4;
    float acc[4][4];
#pragma unroll
    for (int i = 0; i < 4; i++)
#pragma unroll
        for (int j = 0; j < 4; j++) acc[i][j] = 0.f;
    for (int e = 0; e < 64; e++) {
        float qv[4], kv[4];
#pragma unroll
        for (int i = 0; i < 4; i++) qv[i] = Qs[q0 + i][e];
#pragma unroll
        for (int j = 0; j < 4; j++) kv[j] = Ks[k0 + j][e];
#pragma unroll
        for (int i = 0; i < 4; i++)
#pragma unroll
            for (int j = 0; j < 4; j++) acc[i][j] += qv[i] * kv[j];
    }
    bool diag = (kt == qt);
#pragma unroll
    for (int i = 0; i < 4; i++) {
        int qq = qt * 64 + q0 + i;
#pragma unroll
        for (int j = 0; j < 4; j++) {
            int kk = kt * 64 + k0 + j;
            float v = acc[i][j] * 0.125f;
            if (diag && kk > qq) v = -1e30f;
            sc[(size_t)(q0 + i) * SS + (k0 + j)] = v;
        }
    }
}

// ---------------- row softmax over S (masked entries are -1e30) ----------------
__global__ __launch_bounds__(256) void softmax_kernel() {
    size_t row = blockIdx.x;
    float* sc = g_sc + row * SS;
    int tid = threadIdx.x;
    float4 v = *(float4*)&sc[tid * 4];
    __shared__ float red[8];
    __shared__ float stat;
    float m = fmaxf(fmaxf(v.x, v.y), fmaxf(v.z, v.w));
    for (int o = 16; o; o >>= 1) m = fmaxf(m, __shfl_down_sync(~0u, m, o));
    if ((tid & 31) == 0) red[tid >> 5] = m;
    __syncthreads();
    if (tid == 0) {
        float t = red[0];
        for (int i = 1; i < 8; i++) t = fmaxf(t, red[i]);
        stat = t;
    }
    __syncthreads();
    float mx = stat;
    float e0 = expf(v.x - mx), e1 = expf(v.y - mx), e2 = expf(v.z - mx), e3 = expf(v.w - mx);
    float s = e0 + e1 + e2 + e3;
    for (int o = 16; o; o >>= 1) s += __shfl_down_sync(~0u, s, o);
    __syncthreads();
    if ((tid & 31) == 0) red[tid >> 5] = s;
    __syncthreads();
    if (tid == 0) {
        float t = 0.f;
        for (int i = 0; i < 8; i++) t += red[i];
        stat = t;
    }
    __syncthreads();
    float inv = 1.0f / stat;
    *(float4*)&sc[tid * 4] = make_float4(e0 * inv, e1 * inv, e2 * inv, e3 * inv);
}

// ---------------- attention: A = P @ V ----------------
__global__ __launch_bounds__(256) void attn_av_kernel() {
    int qt = blockIdx.x, bh = blockIdx.y;
    int b = bh >> 4, hh = bh & 15;
    int tid = threadIdx.x;
    __shared__ float Ps[64][65];
    __shared__ float Vs[64][65];
    int tx = tid & 15, ty = tid >> 4;
    int q0 = ty * 4, e0 = tx * 4;
    float acc[4][4];
#pragma unroll
    for (int i = 0; i < 4; i++)
#pragma unroll
        for (int j = 0; j < 4; j++) acc[i][j] = 0.f;
    const float* scb = g_sc + ((size_t)bh * SS + qt * 64) * SS;
    for (int kt = 0; kt <= qt; kt++) {
        const float* vb = g_v + ((size_t)(b * SS + kt * 64)) * DD + hh * HD;
        for (int i = tid; i < 64 * 64; i += 256) {
            int r = i >> 6, c = i & 63;
            Ps[r][c] = scb[(size_t)r * SS + kt * 64 + c];
            Vs[r][c] = vb[(size_t)r * DD + c];
        }
        __syncthreads();
        for (int kk = 0; kk < 64; kk++) {
            float pv[4], vv[4];
#pragma unroll
            for (int i = 0; i < 4; i++) pv[i] = Ps[q0 + i][kk];
#pragma unroll
            for (int j = 0; j < 4; j++) vv[j] = Vs[kk][e0 + j];
#pragma unroll
            for (int i = 0; i < 4; i++)
#pragma unroll
                for (int j = 0; j < 4; j++) acc[i][j] += pv[i] * vv[j];
        }
        __syncthreads();
    }
#pragma unroll
    for (int i = 0; i < 4; i++)
#pragma unroll
        for (int j = 0; j < 4; j++)
            g_a[((size_t)(b * SS + qt * 64 + q0 + i)) * DD + hh * HD + e0 + j] = acc[i][j];
}

// ---------------- LayerNorm (row = 1024) ----------------
__global__ __launch_bounds__(256) void ln_kernel(const float* __restrict__ in,
                                                 const float* __restrict__ g,
                                                 const float* __restrict__ bsh,
                                                 float* __restrict__ out) {
    size_t row = blockIdx.x;
    const float* x = in + row * DD;
    int tid = threadIdx.x;
    float4 v = *(const float4*)&x[tid * 4];
    __shared__ float red[8];
    __shared__ float stat;
    float s = v.x + v.y + v.z + v.w;
    for (int o = 16; o; o >>= 1) s += __shfl_down_sync(~0u, s, o);
    if ((tid & 31) == 0) red[tid >> 5] = s;
    __syncthreads();
    if (tid == 0) {
        float t = 0.f;
        for (int i = 0; i < 8; i++) t += red[i];
        stat = t * (1.0f / DD);
    }
    __syncthreads();
    float mu = stat;
    float dx = v.x - mu, dy = v.y - mu, dz = v.z - mu, dw = v.w - mu;
    float ss = dx * dx + dy * dy + dz * dz + dw * dw;
    for (int o = 16; o; o >>= 1) ss += __shfl_down_sync(~0u, ss, o);
    __syncthreads();
    if ((tid & 31) == 0) red[tid >> 5] = ss;
    __syncthreads();
    if (tid == 0) {
        float t = 0.f;
        for (int i = 0; i < 8; i++) t += red[i];
        stat = rsqrtf(t * (1.0f / DD) + 1e-5f);
    }
    __syncthreads();
    float rs = stat;
    float4 gg = *(const float4*)&g[tid * 4];
    float4 bb = *(const float4*)&bsh[tid * 4];
    float4 o4 = make_float4(dx * rs * gg.x + bb.x, dy * rs * gg.y + bb.y,
                            dz * rs * gg.z + bb.z, dw * rs * gg.w + bb.w);
    *(float4*)&out[row * DD + tid * 4] = o4;
}

// ---------------- router head: rlog = zr @ rW2 + rb2 ; argmax ; counters ------
__global__ __launch_bounds__(256) void router2_kernel(const float* __restrict__ rw2,
                                                      const float* __restrict__ rb2) {
    int w = (blockIdx.x * blockDim.x + threadIdx.x) >> 5;
    int lane = threadIdx.x & 31;
    if (w >= MM) return;
    const float* z = g_zr + (size_t)w * RH;
    float s0 = 0.f, s1 = 0.f, s2 = 0.f;
#pragma unroll
    for (int u = 0; u < 4; u++) {
        int j = lane + 32 * u;
        float zv = z[j];
        s0 += zv * rw2[j * 3 + 0];
        s1 += zv * rw2[j * 3 + 1];
        s2 += zv * rw2[j * 3 + 2];
    }
    for (int o = 16; o; o >>= 1) {
        s0 += __shfl_down_sync(~0u, s0, o);
        s1 += __shfl_down_sync(~0u, s1, o);
        s2 += __shfl_down_sync(~0u, s2, o);
    }
    if (lane == 0) {
        s0 += rb2[0]; s1 += rb2[1]; s2 += rb2[2];
        int a = 0; float best = s0;
        if (s1 > best) { best = s1; a = 1; }
        if (s2 > best) { best = s2; a = 2; }
        g_skip[w] = (a == 0);
        atomicAdd(&g_cnt[a], 1);
    }
}

// ---------------- per-token merge: h = skip ? h : ht ----------------
__global__ __launch_bounds__(256) void merge_kernel() {
    int tok = blockIdx.x;
    if (g_skip[tok]) return;
    int tid = threadIdx.x;
    ((float4*)g_h)[(size_t)tok * 256 + tid] = ((float4*)g_ht)[(size_t)tok * 256 + tid];
}

// ---------------- final scalar stats ----------------
__global__ void scalars_kernel(float* out) {
    float fs = (float)g_cnt[0], ff = (float)g_cnt[1], fr = (float)g_cnt[2];
    out[(size_t)MM * VOC + 0] = (ff + fr) / (float)MM;             // effective depth
    out[(size_t)MM * VOC + 1] = fs / (float)(MM * NL);             // skip frac
    out[(size_t)MM * VOC + 2] = ff / (float)(MM * NL);             // fwd frac
    out[(size_t)MM * VOC + 3] = fr / (float)(MM * NL);             // rec frac
}

// ======================= host launch =======================
extern "C" void kernel_launch(void* const* d_in, const int* in_sizes, int n_in,
                              void* d_out, int out_size) {
    const int*   x     = (const int*)d_in[0];
    const float* emb   = (const float*)d_in[1];
    const float* Wq    = (const float*)d_in[2];
    const float* bq    = (const float*)d_in[3];
    const float* Wk    = (const float*)d_in[4];
    const float* bk    = (const float*)d_in[5];
    const float* Wv    = (const float*)d_in[6];
    const float* bv    = (const float*)d_in[7];
    const float* Wo    = (const float*)d_in[8];
    const float* bo    = (const float*)d_in[9];
    const float* ln1g  = (const float*)d_in[10];
    const float* ln1b  = (const float*)d_in[11];
    const float* Wf1   = (const float*)d_in[12];
    const float* bf1   = (const float*)d_in[13];
    const float* Wf2   = (const float*)d_in[14];
    const float* bf2   = (const float*)d_in[15];
    const float* ln2g  = (const float*)d_in[16];
    const float* ln2b  = (const float*)d_in[17];
    const float* rW1   = (const float*)d_in[18];
    const float* rb1   = (const float*)d_in[19];
    const float* rW2   = (const float*)d_in[20];
    const float* rb2   = (const float*)d_in[21];
    const float* Wout  = (const float*)d_in[22];
    const float* bout  = (const float*)d_in[23];
    float* out = (float*)d_out;

    float *h, *h1, *t, *q, *k, *v, *a, *ht, *f1, *zr;
    cudaGetSymbolAddress((void**)&h,  g_h);
    cudaGetSymbolAddress((void**)&h1, g_h1);
    cudaGetSymbolAddress((void**)&t,  g_t);
    cudaGetSymbolAddress((void**)&q,  g_q);
    cudaGetSymbolAddress((void**)&k,  g_k);
    cudaGetSymbolAddress((void**)&v,  g_v);
    cudaGetSymbolAddress((void**)&a,  g_a);
    cudaGetSymbolAddress((void**)&ht, g_ht);
    cudaGetSymbolAddress((void**)&f1, g_f1);
    cudaGetSymbolAddress((void**)&zr, g_zr);

    zero_cnt_kernel<<<1, 32>>>();
    embed_kernel<<<MM, 256>>>(x, emb);

    for (int l = 0; l < NL; l++) {
        // router
        sgemm_kernel<<<dim3(RH / 64, MM / 128), 256>>>(
            h, rW1 + (size_t)l * DD * RH, rb1 + l * RH, nullptr, zr, MM, RH, DD, 1);
        router2_kernel<<<MM / 8, 256>>>(rW2 + (size_t)l * RH * 3, rb2 + l * 3);
        // QKV
        sgemm_kernel<<<dim3(DD / 64, MM / 128), 256>>>(h, Wq, bq, nullptr, q, MM, DD, DD, 0);
        sgemm_kernel<<<dim3(DD / 64, MM / 128), 256>>>(h, Wk, bk, nullptr, k, MM, DD, DD, 0);
        sgemm_kernel<<<dim3(DD / 64, MM / 128), 256>>>(h, Wv, bv, nullptr, v, MM, DD, DD, 0);
        // attention
        attn_scores_kernel<<<dim3(SS / 64, SS / 64, BHT), 256>>>();
        softmax_kernel<<<BHT * SS, 256>>>();
        attn_av_kernel<<<dim3(SS / 64, BHT), 256>>>();
        // O-proj + residual, LN1
        sgemm_kernel<<<dim3(DD / 64, MM / 128), 256>>>(a, Wo, bo, h, t, MM, DD, DD, 0);
        ln_kernel<<<MM, 256>>>(t, ln1g, ln1b, h1);
        // FFN + residual, LN2
        sgemm_kernel<<<dim3(DFF / 64, MM / 128), 256>>>(h1, Wf1, bf1, nullptr, f1, MM, DFF, DD, 1);
        sgemm_kernel<<<dim3(DD / 64, MM / 128), 256>>>(f1, Wf2, bf2, h1, t, MM, DD, DFF, 0);
        ln_kernel<<<MM, 256>>>(t, ln2g, ln2b, ht);
        // per-token skip merge
        merge_kernel<<<MM, 256>>>();
    }

    // logits
    sgemm_kernel<<<dim3(VOC / 64, MM / 128), 256>>>(h, Wout, bout, nullptr, out, MM, VOC, DD, 0);
    scalars_kernel<<<1, 1>>>(out);
}